// round 11
// baseline (speedup 1.0000x reference)
#include <cuda_runtime.h>
#include <cuda_bf16.h>
#include <cstdint>
#include <math.h>

#define D      4096
#define E      512
#define BROWS  8192
#define NQ     (1ull*BROWS*D)
#define NENC   (1ull*BROWS*E)

#define OUT_Q_OFF    1ull
#define OUT_PERP_OFF (1ull + NQ)
#define OUT_ENC_OFF  (2ull + NQ)

#define SCALE   21.1666667f           // 127/6
#define INV2S2  (2.0f/(SCALE*SCALE))  // dist = cnorm - acc*INV2S2
#define MARGIN  20.0f
#define CAP     16

// ---------------- device scratch ----------------
__device__ float              g_cnorm[E];
__device__ uint8_t            g_C8[(size_t)E * D];        // 2 MB s8 codebook
__device__ unsigned long long g_best[BROWS];
__device__ unsigned long long g_cand[(size_t)BROWS * CAP];
__device__ int                g_ccnt[BROWS];
__device__ int                g_counts[E];
__device__ double             g_loss;

#define SWZ128(off) ((off) ^ (((off) >> 3) & 0x70))

__device__ __forceinline__ uint32_t smem_to_u32(const void* p) {
    uint32_t a;
    asm("{ .reg .u64 t; cvta.to.shared.u64 t, %1; cvt.u32.u64 %0, t; }" : "=r"(a) : "l"(p));
    return a;
}

// float4 -> 4 packed s8 bytes via magic-number rounding (all fma-pipe + prmt)
__device__ __forceinline__ uint32_t f4_to_s8(float4 v) {
    float f0 = fmaf(fminf(fmaxf(v.x, -6.f), 6.f), SCALE, 12582912.f);
    float f1 = fmaf(fminf(fmaxf(v.y, -6.f), 6.f), SCALE, 12582912.f);
    float f2 = fmaf(fminf(fmaxf(v.z, -6.f), 6.f), SCALE, 12582912.f);
    float f3 = fmaf(fminf(fmaxf(v.w, -6.f), 6.f), SCALE, 12582912.f);
    uint32_t r01 = __byte_perm(__float_as_uint(f0), __float_as_uint(f1), 0x0040);
    uint32_t r23 = __byte_perm(__float_as_uint(f2), __float_as_uint(f3), 0x0040);
    return __byte_perm(r01, r23, 0x5410);
}

// key packing: monotone float -> u32, argmin with ties -> lowest index
__device__ __forceinline__ unsigned long long make_key(float d, int idx) {
    unsigned int u = __float_as_uint(d);
    u = (u & 0x80000000u) ? ~u : (u | 0x80000000u);
    return ((unsigned long long)u << 32) | (unsigned int)idx;
}
__device__ __forceinline__ float key_to_float(unsigned long long k) {
    unsigned int u = (unsigned int)(k >> 32);
    u = (u & 0x80000000u) ? (u ^ 0x80000000u) : ~u;
    return __uint_as_float(u);
}

// ---------------- init ----------------
__global__ void init_kernel() {
    int i = blockIdx.x * blockDim.x + threadIdx.x;
    if (i < BROWS) { g_best[i] = 0xFFFFFFFFFFFFFFFFull; g_ccnt[i] = 0; }
    if (i < E)     g_counts[i] = 0;
    if (i == 0)    g_loss = 0.0;
}

// ---------------- codebook: s8 convert + exact norms (fused, 1 read) ----------------
__global__ __launch_bounds__(128)
void convCnorm_kernel(const float* __restrict__ C) {
    const int e = blockIdx.x;
    const float4* row = (const float4*)(C + (size_t)e * D);
    uint4* brow = (uint4*)(g_C8 + (size_t)e * D);
    float s = 0.f;
#pragma unroll
    for (int j = threadIdx.x; j < D / 16; j += 128) {   // 2 iters
        float4 v0 = row[j * 4 + 0], v1 = row[j * 4 + 1];
        float4 v2 = row[j * 4 + 2], v3 = row[j * 4 + 3];
        uint4 p;
        p.x = f4_to_s8(v0); p.y = f4_to_s8(v1);
        p.z = f4_to_s8(v2); p.w = f4_to_s8(v3);
        brow[j] = p;
        s += v0.x*v0.x + v0.y*v0.y + v0.z*v0.z + v0.w*v0.w;
        s += v1.x*v1.x + v1.y*v1.y + v1.z*v1.z + v1.w*v1.w;
        s += v2.x*v2.x + v2.y*v2.y + v2.z*v2.z + v2.w*v2.w;
        s += v3.x*v3.x + v3.y*v3.y + v3.z*v3.z + v3.w*v3.w;
    }
    for (int o = 16; o; o >>= 1) s += __shfl_down_sync(0xffffffffu, s, o);
    __shared__ float ws[4];
    if ((threadIdx.x & 31) == 0) ws[threadIdx.x >> 5] = s;
    __syncthreads();
    if (threadIdx.x == 0) g_cnorm[e] = ws[0] + ws[1] + ws[2] + ws[3];
}

// ---------------- mma.sync s8 GEMM + fused argmin/candidates ----------------
// CTA 256 thr = 8 warps (2M x 4N), tile M=128 x N=256, warp tile 64x64.
// K chunk = 128 s8 elements (128B SW128 rows), double-buffered smem.
#define TM 128
#define TN 256
#define CH 128
#define NCHUNK (D / CH)          // 32
#define A_BYTES 16384
#define B_BYTES 32768
#define GEMM_SMEM (2*A_BYTES + 2*B_BYTES)   // 98304

__global__ __launch_bounds__(256, 1)
void gemm_mma_kernel(const float* __restrict__ X) {
    extern __shared__ __align__(1024) char smem[];
    const int tid  = threadIdx.x;
    const int lane = tid & 31;
    const int wid  = tid >> 5;
    const int warpM = wid >> 2;   // 0..1
    const int warpN = wid & 3;    // 0..3
    const int rowBase = blockIdx.y * TM;
    const int colBase = blockIdx.x * TN;

    uint32_t sbA[2] = { smem_to_u32(smem),             smem_to_u32(smem) + A_BYTES };
    uint32_t sbB[2] = { smem_to_u32(smem) + 2*A_BYTES, smem_to_u32(smem) + 2*A_BYTES + B_BYTES };
    char* pA[2] = { smem, smem + A_BYTES };

    const float* Xg0 = X + (size_t)rowBase * D;
    const uint8_t* Cg0 = g_C8 + (size_t)colBase * D;

    // A: 2 thr/row, each covers 64B of packed s8 (16 float4 loads)
    const int ar = tid >> 1, ahalf = tid & 1;
    // B: 8 thr/row (16B each), rows br + i*32
    const int br = tid >> 3, bc16 = tid & 7;

    int acc[4][8][4];
#pragma unroll
    for (int mi = 0; mi < 4; mi++)
#pragma unroll
        for (int ni = 0; ni < 8; ni++)
#pragma unroll
            for (int r = 0; r < 4; r++) acc[mi][ni][r] = 0;

    uint32_t av[16];

    // ---- preload chunk 0 ----
#pragma unroll
    for (int i = 0; i < 8; i++) {
        int r = br + i * 32;
        uint32_t dst = sbB[0] + SWZ128((uint32_t)(r * 128 + bc16 * 16));
        const uint8_t* src = Cg0 + (size_t)r * D + bc16 * 16;
        asm volatile("cp.async.cg.shared.global [%0], [%1], 16;" :: "r"(dst), "l"(src));
    }
    asm volatile("cp.async.commit_group;" ::: "memory");
    {
        const float* asrc = Xg0 + (size_t)ar * D + ahalf * 64;
#pragma unroll
        for (int i = 0; i < 16; i++)
            av[i] = f4_to_s8(*(const float4*)(asrc + i * 4));
    }

    const int a_r = lane & 15;
    const int a_c = (lane >> 4) * 16;
    const int b_n = ((lane >> 4) << 3) + (lane & 7);
    const int b_c = ((lane >> 3) & 1) * 16;

    for (int kt = 0; kt < NCHUNK; kt++) {
        const int buf = kt & 1;

        // STS A chunk kt (4 x uint4, SW128)
#pragma unroll
        for (int i4 = 0; i4 < 4; i4++) {
            uint4 p = make_uint4(av[i4*4+0], av[i4*4+1], av[i4*4+2], av[i4*4+3]);
            uint32_t off = SWZ128((uint32_t)(ar * 128 + ahalf * 64 + i4 * 16));
            *(uint4*)(pA[buf] + off) = p;
        }
        asm volatile("cp.async.wait_group 0;" ::: "memory");
        __syncthreads();

        // prefetch next chunk (overlaps MMA below)
        if (kt + 1 < NCHUNK) {
            const int nb = buf ^ 1;
            const int k0 = (kt + 1) * CH;
#pragma unroll
            for (int i = 0; i < 8; i++) {
                int r = br + i * 32;
                uint32_t dst = sbB[nb] + SWZ128((uint32_t)(r * 128 + bc16 * 16));
                const uint8_t* src = Cg0 + (size_t)r * D + k0 + bc16 * 16;
                asm volatile("cp.async.cg.shared.global [%0], [%1], 16;" :: "r"(dst), "l"(src));
            }
            asm volatile("cp.async.commit_group;" ::: "memory");
            const float* asrc = Xg0 + (size_t)ar * D + k0 + ahalf * 64;
#pragma unroll
            for (int i = 0; i < 16; i++)
                av[i] = f4_to_s8(*(const float4*)(asrc + i * 4));
        }

        // ---- compute: 4 k32 steps ----
        const uint32_t aB = sbA[buf], bB = sbB[buf];
#pragma unroll
        for (int kk = 0; kk < 4; kk++) {
            uint32_t af[4][4], bfr[4][4];
#pragma unroll
            for (int mi = 0; mi < 4; mi++) {
                uint32_t addr = aB + SWZ128((uint32_t)((warpM * 64 + mi * 16 + a_r) * 128 + kk * 32 + a_c));
                asm volatile("ldmatrix.sync.aligned.m8n8.x4.shared.b16 {%0,%1,%2,%3}, [%4];"
                    : "=r"(af[mi][0]), "=r"(af[mi][1]), "=r"(af[mi][2]), "=r"(af[mi][3]) : "r"(addr));
            }
#pragma unroll
            for (int ng = 0; ng < 4; ng++) {
                uint32_t addr = bB + SWZ128((uint32_t)((warpN * 64 + ng * 16 + b_n) * 128 + kk * 32 + b_c));
                asm volatile("ldmatrix.sync.aligned.m8n8.x4.shared.b16 {%0,%1,%2,%3}, [%4];"
                    : "=r"(bfr[ng][0]), "=r"(bfr[ng][1]), "=r"(bfr[ng][2]), "=r"(bfr[ng][3]) : "r"(addr));
            }
#pragma unroll
            for (int mi = 0; mi < 4; mi++)
#pragma unroll
                for (int ng = 0; ng < 4; ng++) {
                    asm volatile("mma.sync.aligned.m16n8k32.row.col.s32.s8.s8.s32 "
                        "{%0,%1,%2,%3}, {%4,%5,%6,%7}, {%8,%9}, {%0,%1,%2,%3};"
                        : "+r"(acc[mi][2*ng][0]), "+r"(acc[mi][2*ng][1]),
                          "+r"(acc[mi][2*ng][2]), "+r"(acc[mi][2*ng][3])
                        : "r"(af[mi][0]), "r"(af[mi][1]), "r"(af[mi][2]), "r"(af[mi][3]),
                          "r"(bfr[ng][0]), "r"(bfr[ng][1]));
                    asm volatile("mma.sync.aligned.m16n8k32.row.col.s32.s8.s8.s32 "
                        "{%0,%1,%2,%3}, {%4,%5,%6,%7}, {%8,%9}, {%0,%1,%2,%3};"
                        : "+r"(acc[mi][2*ng+1][0]), "+r"(acc[mi][2*ng+1][1]),
                          "+r"(acc[mi][2*ng+1][2]), "+r"(acc[mi][2*ng+1][3])
                        : "r"(af[mi][0]), "r"(af[mi][1]), "r"(af[mi][2]), "r"(af[mi][3]),
                          "r"(bfr[ng][2]), "r"(bfr[ng][3]));
                }
        }
    }

    // ---- fused epilogue: per-CTA row argmin + candidate push ----
    __shared__ unsigned long long rowbest[TM];
    for (int i = tid; i < TM; i += 256) rowbest[i] = 0xFFFFFFFFFFFFFFFFull;
    __syncthreads();

    const int g = lane >> 2, t = lane & 3;
#pragma unroll
    for (int mi = 0; mi < 4; mi++) {
#pragma unroll
        for (int rr = 0; rr < 2; rr++) {
            int lrow = warpM * 64 + mi * 16 + rr * 8 + g;
            unsigned long long best = 0xFFFFFFFFFFFFFFFFull;
#pragma unroll
            for (int ni = 0; ni < 8; ni++) {
                int col = colBase + warpN * 64 + ni * 8 + 2 * t;
                float d0 = g_cnorm[col]     - INV2S2 * (float)acc[mi][ni][rr * 2 + 0];
                float d1 = g_cnorm[col + 1] - INV2S2 * (float)acc[mi][ni][rr * 2 + 1];
                unsigned long long k0 = make_key(d0, col);
                unsigned long long k1 = make_key(d1, col + 1);
                if (k0 < best) best = k0;
                if (k1 < best) best = k1;
            }
            atomicMin(&rowbest[lrow], best);
        }
    }
    __syncthreads();
    for (int i = tid; i < TM; i += 256)
        atomicMin(&g_best[rowBase + i], rowbest[i]);

#pragma unroll
    for (int mi = 0; mi < 4; mi++) {
#pragma unroll
        for (int rr = 0; rr < 2; rr++) {
            int lrow = warpM * 64 + mi * 16 + rr * 8 + g;
            int grow = rowBase + lrow;
            float thr = key_to_float(rowbest[lrow]) + MARGIN;
#pragma unroll
            for (int ni = 0; ni < 8; ni++) {
                int col = colBase + warpN * 64 + ni * 8 + 2 * t;
                float d0 = g_cnorm[col]     - INV2S2 * (float)acc[mi][ni][rr * 2 + 0];
                float d1 = g_cnorm[col + 1] - INV2S2 * (float)acc[mi][ni][rr * 2 + 1];
                if (d0 <= thr) {
                    int p = atomicAdd(&g_ccnt[grow], 1);
                    if (p < CAP) g_cand[(size_t)grow * CAP + p] = make_key(d0, col);
                }
                if (d1 <= thr) {
                    int p = atomicAdd(&g_ccnt[grow], 1);
                    if (p < CAP) g_cand[(size_t)grow * CAP + p] = make_key(d1, col + 1);
                }
            }
        }
    }
}

// ---------------- fused rescue + finalize (R1-style 128-thr scalar stores) ----------------
__global__ __launch_bounds__(128)
void epilogue_kernel(const float* __restrict__ X,
                     const float* __restrict__ C,
                     float* __restrict__ out) {
    __shared__ float ws[4];
    __shared__ int   cand[E];
    __shared__ int   ncand;
    __shared__ float xnorm_s;
    __shared__ int   s_idx;

    const int row = blockIdx.x;
    const int tid = threadIdx.x;
    const int lane = tid & 31, wid = tid >> 5;

    const unsigned long long bk = g_best[row];
    const float gd = key_to_float(bk);
    const int gidx = (int)(bk & 0xffffffffull);
    const int cnt = g_ccnt[row];

    if (tid == 0) ncand = 0;
    __syncthreads();
    if (cnt > CAP) {
        for (int i = tid; i < E; i += 128) cand[i] = i;
        if (tid == 0) ncand = E;
    } else {
        if (tid < cnt) {
            unsigned long long k = g_cand[(size_t)row * CAP + tid];
            if (key_to_float(k) <= gd + MARGIN) {
                int p = atomicAdd(&ncand, 1);
                cand[p] = (int)(k & 0xffffffffull);
            }
        }
    }
    __syncthreads();
    int n = ncand;
    const float4* x4 = (const float4*)(X + (size_t)row * D);

    if (n <= 1) {
        if (tid == 0) s_idx = gidx;
        __syncthreads();
    } else {
        float xs = 0.f;
#pragma unroll
        for (int i = tid; i < D / 4; i += 128) {
            float4 xv = x4[i];
            xs += xv.x * xv.x + xv.y * xv.y + xv.z * xv.z + xv.w * xv.w;
        }
        for (int o = 16; o; o >>= 1) xs += __shfl_down_sync(0xffffffffu, xs, o);
        if (lane == 0) ws[wid] = xs;
        __syncthreads();
        if (tid == 0) xnorm_s = ws[0] + ws[1] + ws[2] + ws[3];

        unsigned long long bestE = 0xFFFFFFFFFFFFFFFFull;
        for (int t = 0; t < n; t++) {
            int cidx = cand[t];
            const float4* c4 = (const float4*)(C + (size_t)cidx * D);
            float s = 0.f;
#pragma unroll
            for (int i = tid; i < D / 4; i += 128) {
                float4 xv = x4[i];
                float4 cv = c4[i];
                s += xv.x * cv.x + xv.y * cv.y + xv.z * cv.z + xv.w * cv.w;
            }
            for (int o = 16; o; o >>= 1) s += __shfl_down_sync(0xffffffffu, s, o);
            __syncthreads();
            if (lane == 0) ws[wid] = s;
            __syncthreads();
            if (tid == 0) {
                float dot = ws[0] + ws[1] + ws[2] + ws[3];
                float dist = (xnorm_s + g_cnorm[cidx]) - 2.f * dot;
                unsigned long long kk = make_key(dist, cidx);
                bestE = (kk < bestE) ? kk : bestE;
            }
        }
        if (tid == 0) s_idx = (int)(bestE & 0xffffffffull);
        __syncthreads();
    }

    const int idx = s_idx;

    // ---- finalize (R1-proven pattern: scalar stores, no staging) ----
    const float4* c4 = (const float4*)(C + (size_t)idx * D);
    float* qout = out + OUT_Q_OFF + (size_t)row * D;

    float s = 0.f;
#pragma unroll
    for (int i = tid; i < D / 4; i += 128) {
        float4 xv = x4[i];
        float4 cv = c4[i];
        float d0 = cv.x - xv.x, d1 = cv.y - xv.y, d2 = cv.z - xv.z, d3 = cv.w - xv.w;
        qout[i * 4 + 0] = xv.x + d0;
        qout[i * 4 + 1] = xv.y + d1;
        qout[i * 4 + 2] = xv.z + d2;
        qout[i * 4 + 3] = xv.w + d3;
        s += d0 * d0 + d1 * d1 + d2 * d2 + d3 * d3;
    }
    for (int o = 16; o; o >>= 1) s += __shfl_down_sync(0xffffffffu, s, o);
    if ((tid & 31) == 0) ws[tid >> 5] = s;
    __syncthreads();
    if (tid == 0) {
        atomicAdd(&g_loss, (double)(ws[0] + ws[1] + ws[2] + ws[3]));
        atomicAdd(&g_counts[idx], 1);
    }

    float* enc = out + OUT_ENC_OFF + (size_t)row * E;
#pragma unroll
    for (int j = tid; j < E; j += 128)
        enc[j] = (j == idx) ? 1.0f : 0.0f;
}

// ---------------- scalars ----------------
__global__ void scalars_kernel(float* __restrict__ out) {
    const int e = threadIdx.x;  // 512 threads
    float p = (float)g_counts[e] / (float)BROWS;
    float term = p * logf(p + 1e-10f);
    for (int o = 16; o; o >>= 1) term += __shfl_down_sync(0xffffffffu, term, o);
    __shared__ float ws[16];
    if ((e & 31) == 0) ws[e >> 5] = term;
    __syncthreads();
    if (e == 0) {
        float H = 0.f;
        for (int w = 0; w < 16; w++) H += ws[w];
        out[0] = (float)(1.25 * (g_loss / (double)NQ));
        out[OUT_PERP_OFF] = expf(-H);
    }
}

// ---------------- launch ----------------
extern "C" void kernel_launch(void* const* d_in, const int* in_sizes, int n_in,
                              void* d_out, int out_size) {
    const float* X = (const float*)d_in[0];
    const float* C = (const float*)d_in[1];
    if (n_in >= 2 && in_sizes[0] == E * D && in_sizes[1] == BROWS * D) {
        const float* t = X; X = C; C = t;
    }
    float* out = (float*)d_out;

    static bool attr_done = false;
    if (!attr_done) {
        cudaFuncSetAttribute(gemm_mma_kernel,
                             cudaFuncAttributeMaxDynamicSharedMemorySize, GEMM_SMEM);
        attr_done = true;
    }

    init_kernel<<<BROWS / 256, 256>>>();
    convCnorm_kernel<<<E, 128>>>(C);
    dim3 grid(E / TN, BROWS / TM);   // (2, 64)
    gemm_mma_kernel<<<grid, 256, GEMM_SMEM>>>(X);
    epilogue_kernel<<<BROWS, 128>>>(X, C, out);
    scalars_kernel<<<1, E>>>(out);
}

// round 12
// speedup vs baseline: 1.7133x; 1.7133x over previous
#include <cuda_runtime.h>
#include <cuda_bf16.h>
#include <cstdint>
#include <math.h>

#define D      4096
#define E      512
#define BROWS  8192
#define NQ     (1ull*BROWS*D)
#define NENC   (1ull*BROWS*E)

#define OUT_Q_OFF    1ull
#define OUT_PERP_OFF (1ull + NQ)
#define OUT_ENC_OFF  (2ull + NQ)

#define MARGIN 4.0f
#define CAP    16

// ---------------- device scratch ----------------
__device__ float              g_cnorm[E];
__device__ __nv_bfloat16      g_Cb[(size_t)E * D];       // 4 MB bf16 codebook
__device__ unsigned long long g_best[BROWS];
__device__ unsigned long long g_cand[(size_t)BROWS * CAP];
__device__ int                g_ccnt[BROWS];
__device__ int                g_idx[BROWS];
__device__ int                g_counts[E];
__device__ double             g_xsum;                    // ||X||_F^2

#define SWZ128(off) ((off) ^ (((off) >> 3) & 0x70))

__device__ __forceinline__ uint32_t smem_to_u32(const void* p) {
    uint32_t a;
    asm("{ .reg .u64 t; cvta.to.shared.u64 t, %1; cvt.u32.u64 %0, t; }" : "=r"(a) : "l"(p));
    return a;
}

// key packing: monotone float -> u32, argmin with ties -> lowest index
__device__ __forceinline__ unsigned long long make_key(float d, int idx) {
    unsigned int u = __float_as_uint(d);
    u = (u & 0x80000000u) ? ~u : (u | 0x80000000u);
    return ((unsigned long long)u << 32) | (unsigned int)idx;
}
__device__ __forceinline__ float key_to_float(unsigned long long k) {
    unsigned int u = (unsigned int)(k >> 32);
    u = (u & 0x80000000u) ? (u ^ 0x80000000u) : ~u;
    return __uint_as_float(u);
}

// ---------------- init ----------------
__global__ void init_kernel() {
    int i = blockIdx.x * blockDim.x + threadIdx.x;
    if (i < BROWS) { g_best[i] = 0xFFFFFFFFFFFFFFFFull; g_ccnt[i] = 0; }
    if (i < E)     g_counts[i] = 0;
    if (i == 0)    g_xsum = 0.0;
}

// ---------------- codebook: bf16 convert + exact norms ----------------
__global__ __launch_bounds__(128)
void convCnorm_kernel(const float* __restrict__ C) {
    const int e = blockIdx.x;
    const float4* row = (const float4*)(C + (size_t)e * D);
    uint2* brow = (uint2*)(g_Cb + (size_t)e * D);
    float s = 0.f;
#pragma unroll
    for (int i = threadIdx.x; i < D / 4; i += 128) {
        float4 v = row[i];
        __nv_bfloat162 lo = __floats2bfloat162_rn(v.x, v.y);
        __nv_bfloat162 hi = __floats2bfloat162_rn(v.z, v.w);
        uint2 p; p.x = *(uint32_t*)&lo; p.y = *(uint32_t*)&hi;
        brow[i] = p;
        s += v.x * v.x + v.y * v.y + v.z * v.z + v.w * v.w;
    }
    for (int o = 16; o; o >>= 1) s += __shfl_down_sync(0xffffffffu, s, o);
    __shared__ float ws[4];
    if ((threadIdx.x & 31) == 0) ws[threadIdx.x >> 5] = s;
    __syncthreads();
    if (threadIdx.x == 0) g_cnorm[e] = ws[0] + ws[1] + ws[2] + ws[3];
}

// ---------------- mma.sync bf16 GEMM + argmin/candidates + ||X||^2 ----------------
// R4-proven core: CTA 256 thr = 8 warps (2M x 4N), tile M=128 x N=256,
// warp tile 64x64, K chunk 64 bf16 (SW128), double-buffered smem.
#define TM 128
#define TN 256
#define CH 64
#define NCHUNK (D / CH)
#define A_BYTES 16384
#define B_BYTES 32768
#define GEMM_SMEM (2*A_BYTES + 2*B_BYTES)   // 98304

__global__ __launch_bounds__(256, 1)
void gemm_mma_kernel(const float* __restrict__ X) {
    extern __shared__ __align__(1024) char smem[];
    const int tid  = threadIdx.x;
    const int lane = tid & 31;
    const int wid  = tid >> 5;
    const int warpM = wid >> 2;
    const int warpN = wid & 3;
    const int rowBase = blockIdx.y * TM;
    const int colBase = blockIdx.x * TN;
    const bool doX = (blockIdx.x == 0);

    uint32_t sbA[2] = { smem_to_u32(smem),             smem_to_u32(smem) + A_BYTES };
    uint32_t sbB[2] = { smem_to_u32(smem) + 2*A_BYTES, smem_to_u32(smem) + 2*A_BYTES + B_BYTES };
    char* pA[2] = { smem, smem + A_BYTES };

    const float* Xg0 = X + (size_t)rowBase * D;
    const __nv_bfloat16* Cg0 = g_Cb + (size_t)colBase * D;

    const int ar  = tid >> 4, ac4  = tid & 15;
    const int br  = tid >> 3, bc16 = tid & 7;

    float acc[4][8][4];
#pragma unroll
    for (int mi = 0; mi < 4; mi++)
#pragma unroll
        for (int ni = 0; ni < 8; ni++)
#pragma unroll
            for (int r = 0; r < 4; r++) acc[mi][ni][r] = 0.f;

    float4 av[8];
    float xn = 0.f;

    // ---- preload chunk 0 ----
#pragma unroll
    for (int i = 0; i < 8; i++) {
        int r = br + i * 32;
        uint32_t dst = sbB[0] + SWZ128((uint32_t)(r * 128 + bc16 * 16));
        const __nv_bfloat16* src = Cg0 + (size_t)r * D + bc16 * 8;
        asm volatile("cp.async.cg.shared.global [%0], [%1], 16;" :: "r"(dst), "l"(src));
    }
    asm volatile("cp.async.commit_group;" ::: "memory");
#pragma unroll
    for (int i = 0; i < 8; i++) {
        av[i] = *(const float4*)(Xg0 + (size_t)(ar + i * 16) * D + ac4 * 4);
        if (doX) xn += av[i].x*av[i].x + av[i].y*av[i].y + av[i].z*av[i].z + av[i].w*av[i].w;
    }

    const int a_r = lane & 15;
    const int a_c = (lane >> 4) * 16;
    const int b_n = ((lane >> 4) << 3) + (lane & 7);
    const int b_c = ((lane >> 3) & 1) * 16;

    for (int kt = 0; kt < NCHUNK; kt++) {
        const int buf = kt & 1;

#pragma unroll
        for (int i = 0; i < 8; i++) {
            int r = ar + i * 16;
            __nv_bfloat162 lo = __floats2bfloat162_rn(av[i].x, av[i].y);
            __nv_bfloat162 hi = __floats2bfloat162_rn(av[i].z, av[i].w);
            uint2 p; p.x = *(uint32_t*)&lo; p.y = *(uint32_t*)&hi;
            *(uint2*)(pA[buf] + SWZ128((uint32_t)(r * 128 + ac4 * 8))) = p;
        }
        asm volatile("cp.async.wait_group 0;" ::: "memory");
        __syncthreads();

        if (kt + 1 < NCHUNK) {
            const int nb = buf ^ 1;
            const int k0 = (kt + 1) * CH;
#pragma unroll
            for (int i = 0; i < 8; i++) {
                int r = br + i * 32;
                uint32_t dst = sbB[nb] + SWZ128((uint32_t)(r * 128 + bc16 * 16));
                const __nv_bfloat16* src = Cg0 + (size_t)r * D + k0 + bc16 * 8;
                asm volatile("cp.async.cg.shared.global [%0], [%1], 16;" :: "r"(dst), "l"(src));
            }
            asm volatile("cp.async.commit_group;" ::: "memory");
#pragma unroll
            for (int i = 0; i < 8; i++) {
                av[i] = *(const float4*)(Xg0 + (size_t)(ar + i * 16) * D + k0 + ac4 * 4);
                if (doX) xn += av[i].x*av[i].x + av[i].y*av[i].y + av[i].z*av[i].z + av[i].w*av[i].w;
            }
        }

        const uint32_t aB = sbA[buf], bB = sbB[buf];
#pragma unroll
        for (int kk = 0; kk < 4; kk++) {
            uint32_t af[4][4], bfr[4][4];
#pragma unroll
            for (int mi = 0; mi < 4; mi++) {
                uint32_t addr = aB + SWZ128((uint32_t)((warpM * 64 + mi * 16 + a_r) * 128 + kk * 32 + a_c));
                asm volatile("ldmatrix.sync.aligned.m8n8.x4.shared.b16 {%0,%1,%2,%3}, [%4];"
                    : "=r"(af[mi][0]), "=r"(af[mi][1]), "=r"(af[mi][2]), "=r"(af[mi][3]) : "r"(addr));
            }
#pragma unroll
            for (int ng = 0; ng < 4; ng++) {
                uint32_t addr = bB + SWZ128((uint32_t)((warpN * 64 + ng * 16 + b_n) * 128 + kk * 32 + b_c));
                asm volatile("ldmatrix.sync.aligned.m8n8.x4.shared.b16 {%0,%1,%2,%3}, [%4];"
                    : "=r"(bfr[ng][0]), "=r"(bfr[ng][1]), "=r"(bfr[ng][2]), "=r"(bfr[ng][3]) : "r"(addr));
            }
#pragma unroll
            for (int mi = 0; mi < 4; mi++)
#pragma unroll
                for (int ng = 0; ng < 4; ng++) {
                    asm volatile("mma.sync.aligned.m16n8k16.row.col.f32.bf16.bf16.f32 "
                        "{%0,%1,%2,%3}, {%4,%5,%6,%7}, {%8,%9}, {%0,%1,%2,%3};"
                        : "+f"(acc[mi][2*ng][0]), "+f"(acc[mi][2*ng][1]),
                          "+f"(acc[mi][2*ng][2]), "+f"(acc[mi][2*ng][3])
                        : "r"(af[mi][0]), "r"(af[mi][1]), "r"(af[mi][2]), "r"(af[mi][3]),
                          "r"(bfr[ng][0]), "r"(bfr[ng][1]));
                    asm volatile("mma.sync.aligned.m16n8k16.row.col.f32.bf16.bf16.f32 "
                        "{%0,%1,%2,%3}, {%4,%5,%6,%7}, {%8,%9}, {%0,%1,%2,%3};"
                        : "+f"(acc[mi][2*ng+1][0]), "+f"(acc[mi][2*ng+1][1]),
                          "+f"(acc[mi][2*ng+1][2]), "+f"(acc[mi][2*ng+1][3])
                        : "r"(af[mi][0]), "r"(af[mi][1]), "r"(af[mi][2]), "r"(af[mi][3]),
                          "r"(bfr[ng][2]), "r"(bfr[ng][3]));
                }
        }
    }

    // ---- ||X||^2 partial (loss) ----
    if (doX) {
        for (int o = 16; o; o >>= 1) xn += __shfl_down_sync(0xffffffffu, xn, o);
        if (lane == 0) atomicAdd(&g_xsum, (double)xn);
    }

    // ---- fused epilogue: per-CTA row argmin + candidate push ----
    __shared__ unsigned long long rowbest[TM];
    for (int i = tid; i < TM; i += 256) rowbest[i] = 0xFFFFFFFFFFFFFFFFull;
    __syncthreads();

    const int g = lane >> 2, t = lane & 3;
#pragma unroll
    for (int mi = 0; mi < 4; mi++) {
#pragma unroll
        for (int rr = 0; rr < 2; rr++) {
            int lrow = warpM * 64 + mi * 16 + rr * 8 + g;
            unsigned long long best = 0xFFFFFFFFFFFFFFFFull;
#pragma unroll
            for (int ni = 0; ni < 8; ni++) {
                int col = colBase + warpN * 64 + ni * 8 + 2 * t;
                float d0 = g_cnorm[col]     - 2.f * acc[mi][ni][rr * 2 + 0];
                float d1 = g_cnorm[col + 1] - 2.f * acc[mi][ni][rr * 2 + 1];
                unsigned long long k0 = make_key(d0, col);
                unsigned long long k1 = make_key(d1, col + 1);
                if (k0 < best) best = k0;
                if (k1 < best) best = k1;
            }
            atomicMin(&rowbest[lrow], best);
        }
    }
    __syncthreads();
    for (int i = tid; i < TM; i += 256)
        atomicMin(&g_best[rowBase + i], rowbest[i]);

#pragma unroll
    for (int mi = 0; mi < 4; mi++) {
#pragma unroll
        for (int rr = 0; rr < 2; rr++) {
            int lrow = warpM * 64 + mi * 16 + rr * 8 + g;
            int grow = rowBase + lrow;
            float thr = key_to_float(rowbest[lrow]) + MARGIN;
#pragma unroll
            for (int ni = 0; ni < 8; ni++) {
                int col = colBase + warpN * 64 + ni * 8 + 2 * t;
                float d0 = g_cnorm[col]     - 2.f * acc[mi][ni][rr * 2 + 0];
                float d1 = g_cnorm[col + 1] - 2.f * acc[mi][ni][rr * 2 + 1];
                if (d0 <= thr) {
                    int p = atomicAdd(&g_ccnt[grow], 1);
                    if (p < CAP) g_cand[(size_t)grow * CAP + p] = make_key(d0, col);
                }
                if (d1 <= thr) {
                    int p = atomicAdd(&g_ccnt[grow], 1);
                    if (p < CAP) g_cand[(size_t)grow * CAP + p] = make_key(d1, col + 1);
                }
            }
        }
    }
}

// ---------------- rescue: resolve final indices (X read only for ambiguous rows) ----------------
__global__ __launch_bounds__(128)
void rescue_kernel(const float* __restrict__ X, const float* __restrict__ C) {
    __shared__ int queue[128];
    __shared__ int qn;
    __shared__ int cand[E];
    __shared__ int ncand;
    __shared__ float ws[4];

    const int tid = threadIdx.x;
    const int lane = tid & 31, wid = tid >> 5;
    const int row0 = blockIdx.x * 128;
    const int row = row0 + tid;

    if (tid == 0) qn = 0;
    __syncthreads();

    // per-thread fast path: filter candidates vs global min + MARGIN
    {
        unsigned long long bk = g_best[row];
        float gd = key_to_float(bk);
        int gidx = (int)(bk & 0xffffffffull);
        int cnt = g_ccnt[row];
        bool ambiguous;
        if (cnt > CAP) {
            ambiguous = true;
        } else {
            int nfil = 0;
            for (int j = 0; j < cnt; j++) {
                unsigned long long k = g_cand[(size_t)row * CAP + j];
                if (key_to_float(k) <= gd + MARGIN) nfil++;
            }
            ambiguous = (nfil > 1);
        }
        if (!ambiguous) {
            g_idx[row] = gidx;
            atomicAdd(&g_counts[gidx], 1);
        } else {
            int p = atomicAdd(&qn, 1);
            queue[p] = row;
        }
    }
    __syncthreads();
    const int nq = qn;

    // cooperative exact rescore for ambiguous rows
    for (int qi = 0; qi < nq; qi++) {
        const int r = queue[qi];
        unsigned long long bk = g_best[r];
        float gd = key_to_float(bk);
        int cnt = g_ccnt[r];

        if (tid == 0) ncand = 0;
        __syncthreads();
        if (cnt > CAP) {
            for (int i = tid; i < E; i += 128) cand[i] = i;
            if (tid == 0) ncand = E;
        } else if (tid < cnt) {
            unsigned long long k = g_cand[(size_t)r * CAP + tid];
            if (key_to_float(k) <= gd + MARGIN) {
                int p = atomicAdd(&ncand, 1);
                cand[p] = (int)(k & 0xffffffffull);
            }
        }
        __syncthreads();
        int n = ncand;

        const float4* x4 = (const float4*)(X + (size_t)r * D);
        unsigned long long bestE = 0xFFFFFFFFFFFFFFFFull;
        for (int t = 0; t < n; t++) {
            int cidx = cand[t];
            const float4* c4 = (const float4*)(C + (size_t)cidx * D);
            float s = 0.f;
#pragma unroll
            for (int i = tid; i < D / 4; i += 128) {
                float4 xv = x4[i];
                float4 cv = c4[i];
                s += xv.x * cv.x + xv.y * cv.y + xv.z * cv.z + xv.w * cv.w;
            }
            for (int o = 16; o; o >>= 1) s += __shfl_down_sync(0xffffffffu, s, o);
            __syncthreads();
            if (lane == 0) ws[wid] = s;
            __syncthreads();
            if (tid == 0) {
                float dot = ws[0] + ws[1] + ws[2] + ws[3];
                // xnorm is common across candidates -> drop it
                float dist = g_cnorm[cidx] - 2.f * dot;
                unsigned long long kk = make_key(dist, cidx);
                bestE = (kk < bestE) ? kk : bestE;
            }
        }
        if (tid == 0) {
            int fi = (int)(bestE & 0xffffffffull);
            g_idx[r] = fi;
            atomicAdd(&g_counts[fi], 1);
        }
        __syncthreads();
    }
}

// ---------------- finalize: pure gather + write (no X) ----------------
__global__ __launch_bounds__(128)
void finalize_kernel(const float* __restrict__ C, float* __restrict__ out) {
    const int row = blockIdx.x;
    const int tid = threadIdx.x;
    const int idx = g_idx[row];

    const float4* c4 = (const float4*)(C + (size_t)idx * D);
    float* qo = out + OUT_Q_OFF + (size_t)row * D;
#pragma unroll
    for (int i = tid; i < D / 4; i += 128) {
        float4 v = c4[i];
        qo[i * 4 + 0] = v.x;
        qo[i * 4 + 1] = v.y;
        qo[i * 4 + 2] = v.z;
        qo[i * 4 + 3] = v.w;
    }

    // encodings: base%4==2 -> scalar edges, float4 middle
    float* enc = out + OUT_ENC_OFF + (size_t)row * E;
    if (tid == 0) {
        enc[0]   = (idx == 0)   ? 1.f : 0.f;
        enc[1]   = (idx == 1)   ? 1.f : 0.f;
        enc[510] = (idx == 510) ? 1.f : 0.f;
        enc[511] = (idx == 511) ? 1.f : 0.f;
    }
    for (int i = tid; i < 127; i += 128) {
        int kq = 2 + i * 4;
        float4 v = make_float4((idx == kq) ? 1.f : 0.f, (idx == kq + 1) ? 1.f : 0.f,
                               (idx == kq + 2) ? 1.f : 0.f, (idx == kq + 3) ? 1.f : 0.f);
        *(float4*)(enc + kq) = v;
    }
}

// ---------------- scalars: loss from g_best + xsum; perplexity ----------------
__global__ void scalars_kernel(float* __restrict__ out) {
    const int e = threadIdx.x;  // 512 threads
    // entropy term
    float p = (float)g_counts[e] / (float)BROWS;
    float term = p * logf(p + 1e-10f);
    // distance partial: 16 rows per thread, coalesced stride
    float ds = 0.f;
    for (int j = 0; j < 16; j++)
        ds += key_to_float(g_best[e + j * 512]);
    for (int o = 16; o; o >>= 1) {
        term += __shfl_down_sync(0xffffffffu, term, o);
        ds   += __shfl_down_sync(0xffffffffu, ds, o);
    }
    __shared__ float wt[16];
    __shared__ float wd[16];
    if ((e & 31) == 0) { wt[e >> 5] = term; wd[e >> 5] = ds; }
    __syncthreads();
    if (e == 0) {
        float H = 0.f; double DS = 0.0;
        for (int w = 0; w < 16; w++) { H += wt[w]; DS += (double)wd[w]; }
        out[0] = (float)(1.25 * ((g_xsum + DS) / (double)NQ));
        out[OUT_PERP_OFF] = expf(-H);
    }
}

// ---------------- launch ----------------
extern "C" void kernel_launch(void* const* d_in, const int* in_sizes, int n_in,
                              void* d_out, int out_size) {
    const float* X = (const float*)d_in[0];
    const float* C = (const float*)d_in[1];
    if (n_in >= 2 && in_sizes[0] == E * D && in_sizes[1] == BROWS * D) {
        const float* t = X; X = C; C = t;
    }
    float* out = (float*)d_out;

    static bool attr_done = false;
    if (!attr_done) {
        cudaFuncSetAttribute(gemm_mma_kernel,
                             cudaFuncAttributeMaxDynamicSharedMemorySize, GEMM_SMEM);
        attr_done = true;
    }

    init_kernel<<<BROWS / 256, 256>>>();
    convCnorm_kernel<<<E, 128>>>(C);
    dim3 grid(E / TN, BROWS / TM);   // (2, 64)
    gemm_mma_kernel<<<grid, 256, GEMM_SMEM>>>(X);
    rescue_kernel<<<BROWS / 128, 128>>>(X, C);
    finalize_kernel<<<BROWS, 128>>>(C, out);
    scalars_kernel<<<1, E>>>(out);
}

// round 13
// speedup vs baseline: 2.0886x; 1.2191x over previous
#include <cuda_runtime.h>
#include <cuda_bf16.h>
#include <cstdint>
#include <math.h>

#define D      4096
#define E      512
#define BROWS  8192
#define NQ     (1ull*BROWS*D)
#define NENC   (1ull*BROWS*E)

#define OUT_Q_OFF    1ull
#define OUT_PERP_OFF (1ull + NQ)
#define OUT_ENC_OFF  (2ull + NQ)

#define MARGIN 4.0f
#define CAP    16

// ---------------- device scratch ----------------
__device__ float              g_cnorm[E];
__device__ __nv_bfloat16      g_Cb[(size_t)E * D];       // 4 MB bf16 codebook
__device__ unsigned long long g_best[BROWS];
__device__ unsigned long long g_cand[(size_t)BROWS * CAP];
__device__ int                g_ccnt[BROWS];
__device__ int                g_counts[E];
__device__ double             g_xsum;                    // ||X||_F^2

#define SWZ128(off) ((off) ^ (((off) >> 3) & 0x70))

__device__ __forceinline__ uint32_t smem_to_u32(const void* p) {
    uint32_t a;
    asm("{ .reg .u64 t; cvta.to.shared.u64 t, %1; cvt.u32.u64 %0, t; }" : "=r"(a) : "l"(p));
    return a;
}

// key packing: monotone float -> u32, argmin with ties -> lowest index
__device__ __forceinline__ unsigned long long make_key(float d, int idx) {
    unsigned int u = __float_as_uint(d);
    u = (u & 0x80000000u) ? ~u : (u | 0x80000000u);
    return ((unsigned long long)u << 32) | (unsigned int)idx;
}
__device__ __forceinline__ float key_to_float(unsigned long long k) {
    unsigned int u = (unsigned int)(k >> 32);
    u = (u & 0x80000000u) ? (u ^ 0x80000000u) : ~u;
    return __uint_as_float(u);
}

// ---------------- init ----------------
__global__ void init_kernel() {
    int i = blockIdx.x * blockDim.x + threadIdx.x;
    if (i < BROWS) { g_best[i] = 0xFFFFFFFFFFFFFFFFull; g_ccnt[i] = 0; }
    if (i < E)     g_counts[i] = 0;
    if (i == 0)    g_xsum = 0.0;
}

// ---------------- codebook: bf16 convert + exact norms ----------------
__global__ __launch_bounds__(128)
void convCnorm_kernel(const float* __restrict__ C) {
    const int e = blockIdx.x;
    const float4* row = (const float4*)(C + (size_t)e * D);
    uint2* brow = (uint2*)(g_Cb + (size_t)e * D);
    float s = 0.f;
#pragma unroll
    for (int i = threadIdx.x; i < D / 4; i += 128) {
        float4 v = row[i];
        __nv_bfloat162 lo = __floats2bfloat162_rn(v.x, v.y);
        __nv_bfloat162 hi = __floats2bfloat162_rn(v.z, v.w);
        uint2 p; p.x = *(uint32_t*)&lo; p.y = *(uint32_t*)&hi;
        brow[i] = p;
        s += v.x * v.x + v.y * v.y + v.z * v.z + v.w * v.w;
    }
    for (int o = 16; o; o >>= 1) s += __shfl_down_sync(0xffffffffu, s, o);
    __shared__ float ws[4];
    if ((threadIdx.x & 31) == 0) ws[threadIdx.x >> 5] = s;
    __syncthreads();
    if (threadIdx.x == 0) g_cnorm[e] = ws[0] + ws[1] + ws[2] + ws[3];
}

// ---------------- mma.sync bf16 GEMM + argmin/candidates + ||X||^2 ----------------
#define TM 128
#define TN 256
#define CH 64
#define NCHUNK (D / CH)
#define A_BYTES 16384
#define B_BYTES 32768
#define GEMM_SMEM (2*A_BYTES + 2*B_BYTES)   // 98304

__global__ __launch_bounds__(256, 1)
void gemm_mma_kernel(const float* __restrict__ X) {
    extern __shared__ __align__(1024) char smem[];
    const int tid  = threadIdx.x;
    const int lane = tid & 31;
    const int wid  = tid >> 5;
    const int warpM = wid >> 2;
    const int warpN = wid & 3;
    const int rowBase = blockIdx.y * TM;
    const int colBase = blockIdx.x * TN;
    const bool doX = (blockIdx.x == 0);

    uint32_t sbA[2] = { smem_to_u32(smem),             smem_to_u32(smem) + A_BYTES };
    uint32_t sbB[2] = { smem_to_u32(smem) + 2*A_BYTES, smem_to_u32(smem) + 2*A_BYTES + B_BYTES };
    char* pA[2] = { smem, smem + A_BYTES };

    const float* Xg0 = X + (size_t)rowBase * D;
    const __nv_bfloat16* Cg0 = g_Cb + (size_t)colBase * D;

    const int ar  = tid >> 4, ac4  = tid & 15;
    const int br  = tid >> 3, bc16 = tid & 7;

    float acc[4][8][4];
#pragma unroll
    for (int mi = 0; mi < 4; mi++)
#pragma unroll
        for (int ni = 0; ni < 8; ni++)
#pragma unroll
            for (int r = 0; r < 4; r++) acc[mi][ni][r] = 0.f;

    float4 av[8];
    float xn = 0.f;

#pragma unroll
    for (int i = 0; i < 8; i++) {
        int r = br + i * 32;
        uint32_t dst = sbB[0] + SWZ128((uint32_t)(r * 128 + bc16 * 16));
        const __nv_bfloat16* src = Cg0 + (size_t)r * D + bc16 * 8;
        asm volatile("cp.async.cg.shared.global [%0], [%1], 16;" :: "r"(dst), "l"(src));
    }
    asm volatile("cp.async.commit_group;" ::: "memory");
#pragma unroll
    for (int i = 0; i < 8; i++) {
        av[i] = *(const float4*)(Xg0 + (size_t)(ar + i * 16) * D + ac4 * 4);
        if (doX) xn += av[i].x*av[i].x + av[i].y*av[i].y + av[i].z*av[i].z + av[i].w*av[i].w;
    }

    const int a_r = lane & 15;
    const int a_c = (lane >> 4) * 16;
    const int b_n = ((lane >> 4) << 3) + (lane & 7);
    const int b_c = ((lane >> 3) & 1) * 16;

    for (int kt = 0; kt < NCHUNK; kt++) {
        const int buf = kt & 1;

#pragma unroll
        for (int i = 0; i < 8; i++) {
            int r = ar + i * 16;
            __nv_bfloat162 lo = __floats2bfloat162_rn(av[i].x, av[i].y);
            __nv_bfloat162 hi = __floats2bfloat162_rn(av[i].z, av[i].w);
            uint2 p; p.x = *(uint32_t*)&lo; p.y = *(uint32_t*)&hi;
            *(uint2*)(pA[buf] + SWZ128((uint32_t)(r * 128 + ac4 * 8))) = p;
        }
        asm volatile("cp.async.wait_group 0;" ::: "memory");
        __syncthreads();

        if (kt + 1 < NCHUNK) {
            const int nb = buf ^ 1;
            const int k0 = (kt + 1) * CH;
#pragma unroll
            for (int i = 0; i < 8; i++) {
                int r = br + i * 32;
                uint32_t dst = sbB[nb] + SWZ128((uint32_t)(r * 128 + bc16 * 16));
                const __nv_bfloat16* src = Cg0 + (size_t)r * D + k0 + bc16 * 8;
                asm volatile("cp.async.cg.shared.global [%0], [%1], 16;" :: "r"(dst), "l"(src));
            }
            asm volatile("cp.async.commit_group;" ::: "memory");
#pragma unroll
            for (int i = 0; i < 8; i++) {
                av[i] = *(const float4*)(Xg0 + (size_t)(ar + i * 16) * D + k0 + ac4 * 4);
                if (doX) xn += av[i].x*av[i].x + av[i].y*av[i].y + av[i].z*av[i].z + av[i].w*av[i].w;
            }
        }

        const uint32_t aB = sbA[buf], bB = sbB[buf];
#pragma unroll
        for (int kk = 0; kk < 4; kk++) {
            uint32_t af[4][4], bfr[4][4];
#pragma unroll
            for (int mi = 0; mi < 4; mi++) {
                uint32_t addr = aB + SWZ128((uint32_t)((warpM * 64 + mi * 16 + a_r) * 128 + kk * 32 + a_c));
                asm volatile("ldmatrix.sync.aligned.m8n8.x4.shared.b16 {%0,%1,%2,%3}, [%4];"
                    : "=r"(af[mi][0]), "=r"(af[mi][1]), "=r"(af[mi][2]), "=r"(af[mi][3]) : "r"(addr));
            }
#pragma unroll
            for (int ng = 0; ng < 4; ng++) {
                uint32_t addr = bB + SWZ128((uint32_t)((warpN * 64 + ng * 16 + b_n) * 128 + kk * 32 + b_c));
                asm volatile("ldmatrix.sync.aligned.m8n8.x4.shared.b16 {%0,%1,%2,%3}, [%4];"
                    : "=r"(bfr[ng][0]), "=r"(bfr[ng][1]), "=r"(bfr[ng][2]), "=r"(bfr[ng][3]) : "r"(addr));
            }
#pragma unroll
            for (int mi = 0; mi < 4; mi++)
#pragma unroll
                for (int ng = 0; ng < 4; ng++) {
                    asm volatile("mma.sync.aligned.m16n8k16.row.col.f32.bf16.bf16.f32 "
                        "{%0,%1,%2,%3}, {%4,%5,%6,%7}, {%8,%9}, {%0,%1,%2,%3};"
                        : "+f"(acc[mi][2*ng][0]), "+f"(acc[mi][2*ng][1]),
                          "+f"(acc[mi][2*ng][2]), "+f"(acc[mi][2*ng][3])
                        : "r"(af[mi][0]), "r"(af[mi][1]), "r"(af[mi][2]), "r"(af[mi][3]),
                          "r"(bfr[ng][0]), "r"(bfr[ng][1]));
                    asm volatile("mma.sync.aligned.m16n8k16.row.col.f32.bf16.bf16.f32 "
                        "{%0,%1,%2,%3}, {%4,%5,%6,%7}, {%8,%9}, {%0,%1,%2,%3};"
                        : "+f"(acc[mi][2*ng+1][0]), "+f"(acc[mi][2*ng+1][1]),
                          "+f"(acc[mi][2*ng+1][2]), "+f"(acc[mi][2*ng+1][3])
                        : "r"(af[mi][0]), "r"(af[mi][1]), "r"(af[mi][2]), "r"(af[mi][3]),
                          "r"(bfr[ng][2]), "r"(bfr[ng][3]));
                }
        }
    }

    if (doX) {
        for (int o = 16; o; o >>= 1) xn += __shfl_down_sync(0xffffffffu, xn, o);
        if (lane == 0) atomicAdd(&g_xsum, (double)xn);
    }

    __shared__ unsigned long long rowbest[TM];
    for (int i = tid; i < TM; i += 256) rowbest[i] = 0xFFFFFFFFFFFFFFFFull;
    __syncthreads();

    const int g = lane >> 2, t = lane & 3;
#pragma unroll
    for (int mi = 0; mi < 4; mi++) {
#pragma unroll
        for (int rr = 0; rr < 2; rr++) {
            int lrow = warpM * 64 + mi * 16 + rr * 8 + g;
            unsigned long long best = 0xFFFFFFFFFFFFFFFFull;
#pragma unroll
            for (int ni = 0; ni < 8; ni++) {
                int col = colBase + warpN * 64 + ni * 8 + 2 * t;
                float d0 = g_cnorm[col]     - 2.f * acc[mi][ni][rr * 2 + 0];
                float d1 = g_cnorm[col + 1] - 2.f * acc[mi][ni][rr * 2 + 1];
                unsigned long long k0 = make_key(d0, col);
                unsigned long long k1 = make_key(d1, col + 1);
                if (k0 < best) best = k0;
                if (k1 < best) best = k1;
            }
            atomicMin(&rowbest[lrow], best);
        }
    }
    __syncthreads();
    for (int i = tid; i < TM; i += 256)
        atomicMin(&g_best[rowBase + i], rowbest[i]);

#pragma unroll
    for (int mi = 0; mi < 4; mi++) {
#pragma unroll
        for (int rr = 0; rr < 2; rr++) {
            int lrow = warpM * 64 + mi * 16 + rr * 8 + g;
            int grow = rowBase + lrow;
            float thr = key_to_float(rowbest[lrow]) + MARGIN;
#pragma unroll
            for (int ni = 0; ni < 8; ni++) {
                int col = colBase + warpN * 64 + ni * 8 + 2 * t;
                float d0 = g_cnorm[col]     - 2.f * acc[mi][ni][rr * 2 + 0];
                float d1 = g_cnorm[col + 1] - 2.f * acc[mi][ni][rr * 2 + 1];
                if (d0 <= thr) {
                    int p = atomicAdd(&g_ccnt[grow], 1);
                    if (p < CAP) g_cand[(size_t)grow * CAP + p] = make_key(d0, col);
                }
                if (d1 <= thr) {
                    int p = atomicAdd(&g_ccnt[grow], 1);
                    if (p < CAP) g_cand[(size_t)grow * CAP + p] = make_key(d1, col + 1);
                }
            }
        }
    }
}

// ---------------- fused epilogue: resolve idx (+rare exact rescue) + gather/write ----------------
__global__ __launch_bounds__(128)
void epilogue_kernel(const float* __restrict__ X,
                     const float* __restrict__ C,
                     float* __restrict__ out) {
    __shared__ float ws[4];
    __shared__ int   cand[E];
    __shared__ int   ncand;
    __shared__ int   s_idx;

    const int row = blockIdx.x;
    const int tid = threadIdx.x;
    const int lane = tid & 31, wid = tid >> 5;

    const unsigned long long bk = g_best[row];
    const float gd = key_to_float(bk);
    const int gidx = (int)(bk & 0xffffffffull);
    const int cnt = g_ccnt[row];

    if (tid == 0) ncand = 0;
    __syncthreads();
    if (cnt > CAP) {
        for (int i = tid; i < E; i += 128) cand[i] = i;
        if (tid == 0) ncand = E;
    } else if (tid < cnt) {
        unsigned long long k = g_cand[(size_t)row * CAP + tid];
        if (key_to_float(k) <= gd + MARGIN) {
            int p = atomicAdd(&ncand, 1);
            cand[p] = (int)(k & 0xffffffffull);
        }
    }
    __syncthreads();
    const int n = ncand;

    if (n <= 1) {
        if (tid == 0) s_idx = gidx;
    } else {
        // exact rescoring (X read only here; xnorm common -> dropped)
        const float4* x4 = (const float4*)(X + (size_t)row * D);
        unsigned long long bestE = 0xFFFFFFFFFFFFFFFFull;
        for (int t = 0; t < n; t++) {
            int cidx = cand[t];
            const float4* c4 = (const float4*)(C + (size_t)cidx * D);
            float s = 0.f;
#pragma unroll
            for (int i = tid; i < D / 4; i += 128) {
                float4 xv = x4[i];
                float4 cv = c4[i];
                s += xv.x * cv.x + xv.y * cv.y + xv.z * cv.z + xv.w * cv.w;
            }
            for (int o = 16; o; o >>= 1) s += __shfl_down_sync(0xffffffffu, s, o);
            __syncthreads();
            if (lane == 0) ws[wid] = s;
            __syncthreads();
            if (tid == 0) {
                float dot = ws[0] + ws[1] + ws[2] + ws[3];
                float dist = g_cnorm[cidx] - 2.f * dot;
                unsigned long long kk = make_key(dist, cidx);
                bestE = (kk < bestE) ? kk : bestE;
            }
        }
        if (tid == 0) s_idx = (int)(bestE & 0xffffffffull);
    }
    __syncthreads();
    const int idx = s_idx;
    if (tid == 0) atomicAdd(&g_counts[idx], 1);

    // ---- gather + write (no X): quantized_st == C[idx] to 1 ulp ----
    const float4* c4 = (const float4*)(C + (size_t)idx * D);
    float* qo = out + OUT_Q_OFF + (size_t)row * D;
#pragma unroll
    for (int i = tid; i < D / 4; i += 128) {
        float4 v = c4[i];
        qo[i * 4 + 0] = v.x;
        qo[i * 4 + 1] = v.y;
        qo[i * 4 + 2] = v.z;
        qo[i * 4 + 3] = v.w;
    }

    // encodings: base%4==2 -> scalar edges, float4 middle
    float* enc = out + OUT_ENC_OFF + (size_t)row * E;
    if (tid == 0) {
        enc[0]   = (idx == 0)   ? 1.f : 0.f;
        enc[1]   = (idx == 1)   ? 1.f : 0.f;
        enc[510] = (idx == 510) ? 1.f : 0.f;
        enc[511] = (idx == 511) ? 1.f : 0.f;
    }
    for (int i = tid; i < 127; i += 128) {
        int kq = 2 + i * 4;
        float4 v = make_float4((idx == kq) ? 1.f : 0.f, (idx == kq + 1) ? 1.f : 0.f,
                               (idx == kq + 2) ? 1.f : 0.f, (idx == kq + 3) ? 1.f : 0.f);
        *(float4*)(enc + kq) = v;
    }
}

// ---------------- scalars: loss from g_best + xsum; perplexity ----------------
__global__ void scalars_kernel(float* __restrict__ out) {
    const int e = threadIdx.x;  // 512 threads
    float p = (float)g_counts[e] / (float)BROWS;
    float term = p * logf(p + 1e-10f);
    float ds = 0.f;
    for (int j = 0; j < 16; j++)
        ds += key_to_float(g_best[e + j * 512]);
    for (int o = 16; o; o >>= 1) {
        term += __shfl_down_sync(0xffffffffu, term, o);
        ds   += __shfl_down_sync(0xffffffffu, ds, o);
    }
    __shared__ float wt[16];
    __shared__ float wd[16];
    if ((e & 31) == 0) { wt[e >> 5] = term; wd[e >> 5] = ds; }
    __syncthreads();
    if (e == 0) {
        float H = 0.f; double DS = 0.0;
        for (int w = 0; w < 16; w++) { H += wt[w]; DS += (double)wd[w]; }
        out[0] = (float)(1.25 * ((g_xsum + DS) / (double)NQ));
        out[OUT_PERP_OFF] = expf(-H);
    }
}

// ---------------- launch ----------------
extern "C" void kernel_launch(void* const* d_in, const int* in_sizes, int n_in,
                              void* d_out, int out_size) {
    const float* X = (const float*)d_in[0];
    const float* C = (const float*)d_in[1];
    if (n_in >= 2 && in_sizes[0] == E * D && in_sizes[1] == BROWS * D) {
        const float* t = X; X = C; C = t;
    }
    float* out = (float*)d_out;

    static bool attr_done = false;
    if (!attr_done) {
        cudaFuncSetAttribute(gemm_mma_kernel,
                             cudaFuncAttributeMaxDynamicSharedMemorySize, GEMM_SMEM);
        attr_done = true;
    }

    init_kernel<<<BROWS / 256, 256>>>();
    convCnorm_kernel<<<E, 128>>>(C);
    dim3 grid(E / TN, BROWS / TM);   // (2, 64)
    gemm_mma_kernel<<<grid, 256, GEMM_SMEM>>>(X);
    epilogue_kernel<<<BROWS, 128>>>(X, C, out);
    scalars_kernel<<<1, E>>>(out);
}